// round 5
// baseline (speedup 1.0000x reference)
#include <cuda_runtime.h>

// D is fixed by the problem (256 floats per row).
#define D 256
#define GMAX 8192

// Scratch (no cudaMalloc allowed): inverse norms of the two target matrices,
// plus a double accumulator for the global sum.
__device__ float  d_ginv1[GMAX];
__device__ float  d_ginv2[GMAX];
__device__ double d_acc;

// ---------------------------------------------------------------------------
// Kernel 1: zero the accumulator and precompute 1 / max(||g_r||, 1e-12)
// for both target matrices. One warp per row, 2 float4 loads per lane.
// ---------------------------------------------------------------------------
__global__ __launch_bounds__(256) void init_k(const float* __restrict__ g1,
                                              const float* __restrict__ g2,
                                              int G)
{
    if (blockIdx.x == 0 && threadIdx.x == 0) d_acc = 0.0;

    const int lane = threadIdx.x & 31;
    const int warp = (blockIdx.x * blockDim.x + threadIdx.x) >> 5;
    const int nw   = (gridDim.x * blockDim.x) >> 5;

    for (int r = warp; r < G; r += nw) {
        const float4* p1 = reinterpret_cast<const float4*>(g1 + (size_t)r * D);
        const float4* p2 = reinterpret_cast<const float4*>(g2 + (size_t)r * D);
        float s1 = 0.f, s2 = 0.f;
#pragma unroll
        for (int j = 0; j < 2; ++j) {
            float4 a = p1[lane + 32 * j];
            float4 b = p2[lane + 32 * j];
            s1 += a.x * a.x + a.y * a.y + a.z * a.z + a.w * a.w;
            s2 += b.x * b.x + b.y * b.y + b.z * b.z + b.w * b.w;
        }
#pragma unroll
        for (int off = 16; off > 0; off >>= 1) {
            s1 += __shfl_xor_sync(0xffffffffu, s1, off);
            s2 += __shfl_xor_sync(0xffffffffu, s2, off);
        }
        if (lane == 0) {
            // 1/max(sqrt(s), 1e-12): for s > 1e-24 this is exactly rsqrt(s).
            d_ginv1[r] = rsqrtf(fmaxf(s1, 1e-24f));
            d_ginv2[r] = rsqrtf(fmaxf(s2, 1e-24f));
        }
    }
}

// ---------------------------------------------------------------------------
// Kernel 2: main reduction.
//   total = sum_i  dot(h1_i, g2_b)/||h1_i|| * ginv2[b]
//               +  dot(h2_i, g1_b)/||h2_i|| * ginv1[b],   b = batch[i]
// One warp per row (grid-stride). 8 LDG.128 per lane per row (MLP=8).
// batch is sorted, so g rows hit L1/L2 across consecutive warps.
// Per-warp accumulation in double; one atomicAdd(double) per block.
// ---------------------------------------------------------------------------
__global__ __launch_bounds__(256) void main_k(const float* __restrict__ h1,
                                              const float* __restrict__ h2,
                                              const float* __restrict__ g1,
                                              const float* __restrict__ g2,
                                              const int*   __restrict__ batch,
                                              int N)
{
    const int lane = threadIdx.x & 31;
    const int wid  = threadIdx.x >> 5;
    const int warp = (blockIdx.x * blockDim.x + threadIdx.x) >> 5;
    const int nw   = (gridDim.x * blockDim.x) >> 5;

    double acc = 0.0;

    for (int i = warp; i < N; i += nw) {
        const int b = batch[i];
        const float4* ph1 = reinterpret_cast<const float4*>(h1 + (size_t)i * D);
        const float4* ph2 = reinterpret_cast<const float4*>(h2 + (size_t)i * D);
        const float4* pg1 = reinterpret_cast<const float4*>(g1 + (size_t)b * D);
        const float4* pg2 = reinterpret_cast<const float4*>(g2 + (size_t)b * D);

        float d1 = 0.f, s1 = 0.f, d2 = 0.f, s2 = 0.f;
#pragma unroll
        for (int j = 0; j < 2; ++j) {
            const int idx = lane + 32 * j;
            float4 a = ph1[idx];   // h1 row
            float4 c = pg2[idx];   // g2 row (pairs with h1)
            float4 e = ph2[idx];   // h2 row
            float4 f = pg1[idx];   // g1 row (pairs with h2)
            s1 += a.x * a.x + a.y * a.y + a.z * a.z + a.w * a.w;
            d1 += a.x * c.x + a.y * c.y + a.z * c.z + a.w * c.w;
            s2 += e.x * e.x + e.y * e.y + e.z * e.z + e.w * e.w;
            d2 += e.x * f.x + e.y * f.y + e.z * f.z + e.w * f.w;
        }
#pragma unroll
        for (int off = 16; off > 0; off >>= 1) {
            d1 += __shfl_xor_sync(0xffffffffu, d1, off);
            s1 += __shfl_xor_sync(0xffffffffu, s1, off);
            d2 += __shfl_xor_sync(0xffffffffu, d2, off);
            s2 += __shfl_xor_sync(0xffffffffu, s2, off);
        }
        if (lane == 0) {
            float v = d1 * rsqrtf(fmaxf(s1, 1e-24f)) * d_ginv2[b]
                    + d2 * rsqrtf(fmaxf(s2, 1e-24f)) * d_ginv1[b];
            acc += (double)v;
        }
    }

    __shared__ double sred[8];
    if (lane == 0) sred[wid] = acc;
    __syncthreads();
    if (threadIdx.x == 0) {
        double t = 0.0;
#pragma unroll
        for (int w = 0; w < 8; ++w) t += sred[w];
        atomicAdd(&d_acc, t);
    }
}

// ---------------------------------------------------------------------------
// Kernel 3: epilogue — write mean as float.
// ---------------------------------------------------------------------------
__global__ void finish_k(float* __restrict__ out, int G)
{
    *out = (float)(d_acc / (double)G);
}

extern "C" void kernel_launch(void* const* d_in, const int* in_sizes, int n_in,
                              void* d_out, int out_size)
{
    const float* h1    = (const float*)d_in[0];
    const float* h2    = (const float*)d_in[1];
    const float* g1    = (const float*)d_in[2];
    const float* g2    = (const float*)d_in[3];
    const int*   batch = (const int*)d_in[4];   // jax default int32 (x64 disabled)

    const int N = in_sizes[4];          // rows in h1/h2
    const int G = in_sizes[2] / D;      // rows in g1/g2

    init_k<<<64, 256>>>(g1, g2, G);
    main_k<<<1520, 256>>>(h1, h2, g1, g2, batch, N);
    finish_k<<<1, 1>>>((float*)d_out, G);
}

// round 6
// speedup vs baseline: 1.4132x; 1.4132x over previous
#include <cuda_runtime.h>

// D fixed by the problem (256 floats per row).
#define D     256
#define NBLK  1520

// Per-block partial sums (written every call -> no zeroing, no atomics).
__device__ double d_part[NBLK];

__device__ __forceinline__ float dot4(float4 a, float4 b) {
    return a.x * b.x + a.y * b.y + a.z * b.z + a.w * b.w;
}

// ---------------------------------------------------------------------------
// Main kernel: one warp per contiguous chunk of rows.
//   total = sum_i  dot(h1_i, g2_b) * ginv(h1_i) * ginv(g2_b)
//               +  dot(h2_i, g1_b) * ginv(h2_i) * ginv(g1_b),  b = batch[i]
// batch is sorted, so within a contiguous chunk b rarely changes: the two
// 1 KB g rows live in registers and their inverse norms are computed inline
// on each (rare) b change. 8 LDG.128 per lane per row (h1+h2 only).
// ---------------------------------------------------------------------------
__global__ __launch_bounds__(256) void main_k(const float* __restrict__ h1,
                                              const float* __restrict__ h2,
                                              const float* __restrict__ g1,
                                              const float* __restrict__ g2,
                                              const int*   __restrict__ batch,
                                              int N)
{
    const int lane  = threadIdx.x & 31;
    const int wid   = threadIdx.x >> 5;
    const int gwarp = blockIdx.x * 8 + wid;
    const int nw    = gridDim.x * 8;

    const int per = (N + nw - 1) / nw;
    const int i0  = gwarp * per;
    const int i1  = min(N, i0 + per);

    double acc = 0.0;

    int   bcur = -1;
    float gi1 = 0.f, gi2 = 0.f;               // lane-uniform inverse norms
    float4 fg0, fg1, cg0, cg1;                // cached g1/g2 rows (this lane's slice)
    fg0 = fg1 = cg0 = cg1 = make_float4(0.f, 0.f, 0.f, 0.f);

    for (int i = i0; i < i1; ++i) {
        const int b = batch[i];               // warp-uniform broadcast load

        if (b != bcur) {                      // warp-uniform branch, rare
            bcur = b;
            const float4* pg1 = reinterpret_cast<const float4*>(g1 + (size_t)b * D);
            const float4* pg2 = reinterpret_cast<const float4*>(g2 + (size_t)b * D);
            fg0 = pg1[lane]; fg1 = pg1[lane + 32];
            cg0 = pg2[lane]; cg1 = pg2[lane + 32];
            float sg1 = dot4(fg0, fg0) + dot4(fg1, fg1);
            float sg2 = dot4(cg0, cg0) + dot4(cg1, cg1);
#pragma unroll
            for (int off = 16; off > 0; off >>= 1) {
                sg1 += __shfl_xor_sync(0xffffffffu, sg1, off);
                sg2 += __shfl_xor_sync(0xffffffffu, sg2, off);
            }
            // 1/max(||g||, 1e-12) == rsqrt(max(s, 1e-24)) for these magnitudes
            gi1 = rsqrtf(fmaxf(sg1, 1e-24f));
            gi2 = rsqrtf(fmaxf(sg2, 1e-24f));
        }

        const float4* ph1 = reinterpret_cast<const float4*>(h1 + (size_t)i * D);
        const float4* ph2 = reinterpret_cast<const float4*>(h2 + (size_t)i * D);
        float4 a0 = ph1[lane], a1 = ph1[lane + 32];
        float4 e0 = ph2[lane], e1 = ph2[lane + 32];

        float d1 = dot4(a0, cg0) + dot4(a1, cg1);
        float s1 = dot4(a0, a0)  + dot4(a1, a1);
        float d2 = dot4(e0, fg0) + dot4(e1, fg1);
        float s2 = dot4(e0, e0)  + dot4(e1, e1);

#pragma unroll
        for (int off = 16; off > 0; off >>= 1) {
            d1 += __shfl_xor_sync(0xffffffffu, d1, off);
            s1 += __shfl_xor_sync(0xffffffffu, s1, off);
            d2 += __shfl_xor_sync(0xffffffffu, d2, off);
            s2 += __shfl_xor_sync(0xffffffffu, s2, off);
        }

        // identical on all lanes after the xor-reduction
        float v = d1 * rsqrtf(fmaxf(s1, 1e-24f)) * gi2
                + d2 * rsqrtf(fmaxf(s2, 1e-24f)) * gi1;
        acc += (double)v;
    }

    __shared__ double sred[8];
    if (lane == 0) sred[wid] = acc;
    __syncthreads();
    if (threadIdx.x == 0) {
        double t = 0.0;
#pragma unroll
        for (int w = 0; w < 8; ++w) t += sred[w];
        d_part[blockIdx.x] = t;               // every slot written every call
    }
}

// ---------------------------------------------------------------------------
// Epilogue: fixed-order deterministic sum of the 1520 block partials.
// ---------------------------------------------------------------------------
__global__ __launch_bounds__(256) void finish_k(float* __restrict__ out, int G)
{
    __shared__ double s[256];
    double t = 0.0;
    for (int i = threadIdx.x; i < NBLK; i += 256) t += d_part[i];
    s[threadIdx.x] = t;
    __syncthreads();
#pragma unroll
    for (int off = 128; off > 0; off >>= 1) {
        if (threadIdx.x < off) s[threadIdx.x] += s[threadIdx.x + off];
        __syncthreads();
    }
    if (threadIdx.x == 0) *out = (float)(s[0] / (double)G);
}

extern "C" void kernel_launch(void* const* d_in, const int* in_sizes, int n_in,
                              void* d_out, int out_size)
{
    const float* h1    = (const float*)d_in[0];
    const float* h2    = (const float*)d_in[1];
    const float* g1    = (const float*)d_in[2];
    const float* g2    = (const float*)d_in[3];
    const int*   batch = (const int*)d_in[4];   // jax default int32 (x64 disabled)

    const int N = in_sizes[4];          // rows in h1/h2
    const int G = in_sizes[2] / D;      // rows in g1/g2

    main_k<<<NBLK, 256>>>(h1, h2, g1, g2, batch, N);
    finish_k<<<1, 256>>>((float*)d_out, G);
}

// round 8
// speedup vs baseline: 1.4250x; 1.0083x over previous
#include <cuda_runtime.h>

// D fixed by the problem (256 floats per row).
#define D     256
#define NBLK  1520

// Per-block partial sums (every slot written every call -> no zeroing needed).
__device__ double   d_part[NBLK];
// Completion counter: starts 0 (static init), incremented to NBLK each call,
// reset to 0 by the last block -> deterministic across graph replays.
__device__ unsigned d_count;

__device__ __forceinline__ float dot4(float4 a, float4 b) {
    return a.x * b.x + a.y * b.y + a.z * b.z + a.w * b.w;
}

// ---------------------------------------------------------------------------
// Fused kernel: one warp per contiguous chunk of rows, last block reduces.
//   total = sum_i  dot(h1_i, g2_b) * ginv(h1_i) * ginv(g2_b)
//               +  dot(h2_i, g1_b) * ginv(h2_i) * ginv(g1_b),  b = batch[i]
// batch is sorted, so within a contiguous chunk b rarely changes: the two
// 1 KB g rows live in registers; their inverse norms are computed inline on
// each (rare) b change. h traffic uses streaming (.cs) loads hoisted above
// the b-change branch for max MLP.
// ---------------------------------------------------------------------------
__global__ __launch_bounds__(256) void main_k(const float* __restrict__ h1,
                                              const float* __restrict__ h2,
                                              const float* __restrict__ g1,
                                              const float* __restrict__ g2,
                                              const int*   __restrict__ batch,
                                              float* __restrict__ out,
                                              int N, int G)
{
    const int lane  = threadIdx.x & 31;
    const int wid   = threadIdx.x >> 5;
    const int gwarp = blockIdx.x * 8 + wid;
    const int nw    = gridDim.x * 8;

    const int per = (N + nw - 1) / nw;
    const int i0  = gwarp * per;
    const int i1  = min(N, i0 + per);

    double acc = 0.0;

    int   bcur = -1;
    float gi1 = 0.f, gi2 = 0.f;               // lane-uniform inverse norms
    float4 fg0, fg1, cg0, cg1;                // cached g1/g2 rows (this lane's slice)
    fg0 = fg1 = cg0 = cg1 = make_float4(0.f, 0.f, 0.f, 0.f);

    for (int i = i0; i < i1; ++i) {
        const int b = batch[i];               // warp-uniform broadcast load

        // h loads hoisted above the branch: independent, issue early (MLP=4),
        // evict-first so the 1 GB stream doesn't churn L2.
        const float4* ph1 = reinterpret_cast<const float4*>(h1 + (size_t)i * D);
        const float4* ph2 = reinterpret_cast<const float4*>(h2 + (size_t)i * D);
        float4 a0 = __ldcs(ph1 + lane), a1 = __ldcs(ph1 + lane + 32);
        float4 e0 = __ldcs(ph2 + lane), e1 = __ldcs(ph2 + lane + 32);

        if (b != bcur) {                      // warp-uniform branch, rare (~1/61)
            bcur = b;
            const float4* pg1 = reinterpret_cast<const float4*>(g1 + (size_t)b * D);
            const float4* pg2 = reinterpret_cast<const float4*>(g2 + (size_t)b * D);
            fg0 = pg1[lane]; fg1 = pg1[lane + 32];
            cg0 = pg2[lane]; cg1 = pg2[lane + 32];
            float sg1 = dot4(fg0, fg0) + dot4(fg1, fg1);
            float sg2 = dot4(cg0, cg0) + dot4(cg1, cg1);
#pragma unroll
            for (int off = 16; off > 0; off >>= 1) {
                sg1 += __shfl_xor_sync(0xffffffffu, sg1, off);
                sg2 += __shfl_xor_sync(0xffffffffu, sg2, off);
            }
            // 1/max(||g||, 1e-12) == rsqrt(max(s, 1e-24)) for these magnitudes
            gi1 = rsqrtf(fmaxf(sg1, 1e-24f));
            gi2 = rsqrtf(fmaxf(sg2, 1e-24f));
        }

        float d1 = dot4(a0, cg0) + dot4(a1, cg1);
        float s1 = dot4(a0, a0)  + dot4(a1, a1);
        float d2 = dot4(e0, fg0) + dot4(e1, fg1);
        float s2 = dot4(e0, e0)  + dot4(e1, e1);

#pragma unroll
        for (int off = 16; off > 0; off >>= 1) {
            d1 += __shfl_xor_sync(0xffffffffu, d1, off);
            s1 += __shfl_xor_sync(0xffffffffu, s1, off);
            d2 += __shfl_xor_sync(0xffffffffu, d2, off);
            s2 += __shfl_xor_sync(0xffffffffu, s2, off);
        }

        // identical on all lanes after the xor-reduction
        float v = d1 * rsqrtf(fmaxf(s1, 1e-24f)) * gi2
                + d2 * rsqrtf(fmaxf(s2, 1e-24f)) * gi1;
        acc += (double)v;
    }

    // ---- block-level partial ----
    __shared__ double sred[8];
    __shared__ bool   is_last;
    if (lane == 0) sred[wid] = acc;
    __syncthreads();
    if (threadIdx.x == 0) {
        double t = 0.0;
#pragma unroll
        for (int w = 0; w < 8; ++w) t += sred[w];
        d_part[blockIdx.x] = t;
        __threadfence();                       // make d_part visible device-wide
        unsigned prev = atomicAdd(&d_count, 1u);
        is_last = (prev == (unsigned)(NBLK - 1));
    }
    __syncthreads();

    // ---- last block: fixed-order deterministic final reduction ----
    if (is_last) {
        __shared__ double s[256];
        double t = 0.0;
        for (int i = threadIdx.x; i < NBLK; i += 256)
            t += __ldcg(&d_part[i]);           // L2-coherent reads
        s[threadIdx.x] = t;
        __syncthreads();
#pragma unroll
        for (int off = 128; off > 0; off >>= 1) {
            if (threadIdx.x < off) s[threadIdx.x] += s[threadIdx.x + off];
            __syncthreads();
        }
        if (threadIdx.x == 0) {
            *out = (float)(s[0] / (double)G);
            d_count = 0;                       // reset for next graph replay
        }
    }
}

extern "C" void kernel_launch(void* const* d_in, const int* in_sizes, int n_in,
                              void* d_out, int out_size)
{
    const float* h1    = (const float*)d_in[0];
    const float* h2    = (const float*)d_in[1];
    const float* g1    = (const float*)d_in[2];
    const float* g2    = (const float*)d_in[3];
    const int*   batch = (const int*)d_in[4];   // jax default int32 (x64 disabled)

    const int N = in_sizes[4];          // rows in h1/h2
    const int G = in_sizes[2] / D;      // rows in g1/g2

    main_k<<<NBLK, 256>>>(h1, h2, g1, g2, batch, (float*)d_out, N, G);
}

// round 9
// speedup vs baseline: 1.6383x; 1.1497x over previous
#include <cuda_runtime.h>

// D fixed by the problem (256 floats per row).
#define D     256
#define TPB   128
#define WPB   (TPB / 32)
#define NBLK  1064            // 152 SMs x 7 resident blocks: one persistent wave

// Per-block partial sums (every slot written every call -> no zeroing needed).
__device__ double   d_part[NBLK];
// Completion counter: 0 at start, last block resets it -> replay-deterministic.
__device__ unsigned d_count;

__device__ __forceinline__ float dot4(float4 a, float4 b) {
    return a.x * b.x + a.y * b.y + a.z * b.z + a.w * b.w;
}

// ---------------------------------------------------------------------------
// Persistent single-wave kernel, rows processed in pairs per warp.
//   total = sum_i  dot(h1_i, g2_b)*ginv(h1_i)*ginv(g2_b)
//               +  dot(h2_i, g1_b)*ginv(h2_i)*ginv(g1_b),   b = batch[i]
// batch is sorted: the two 1 KB g rows live in registers, reloaded only on
// (rare) b change; inverse norms computed inline at that point. 8 LDG.128
// batched per pair; two 4-value shuffle chains interleaved for ILP.
// ---------------------------------------------------------------------------
__global__ void __launch_bounds__(TPB, 7)
main_k(const float* __restrict__ h1, const float* __restrict__ h2,
       const float* __restrict__ g1, const float* __restrict__ g2,
       const int*   __restrict__ batch, float* __restrict__ out,
       int N, int G)
{
    const int lane  = threadIdx.x & 31;
    const int wid   = threadIdx.x >> 5;
    const int gwarp = blockIdx.x * WPB + wid;
    const int nw    = gridDim.x * WPB;

    const int per = (N + nw - 1) / nw;
    const int i0  = gwarp * per;
    const int i1  = min(N, i0 + per);

    double acc = 0.0;

    int   bcur = -1;
    float gi1 = 0.f, gi2 = 0.f;               // lane-uniform inverse norms
    float4 fg0, fg1, cg0, cg1;                // cached g1/g2 rows (lane slice)
    fg0 = fg1 = cg0 = cg1 = make_float4(0.f, 0.f, 0.f, 0.f);

#define RELOAD_G(B)                                                          \
    do {                                                                     \
        bcur = (B);                                                          \
        const float4* pg1 = reinterpret_cast<const float4*>(g1 + (size_t)bcur * D); \
        const float4* pg2 = reinterpret_cast<const float4*>(g2 + (size_t)bcur * D); \
        fg0 = pg1[lane]; fg1 = pg1[lane + 32];                               \
        cg0 = pg2[lane]; cg1 = pg2[lane + 32];                               \
        float sg1 = dot4(fg0, fg0) + dot4(fg1, fg1);                         \
        float sg2 = dot4(cg0, cg0) + dot4(cg1, cg1);                         \
        _Pragma("unroll")                                                    \
        for (int off = 16; off > 0; off >>= 1) {                             \
            sg1 += __shfl_xor_sync(0xffffffffu, sg1, off);                   \
            sg2 += __shfl_xor_sync(0xffffffffu, sg2, off);                   \
        }                                                                    \
        gi1 = rsqrtf(fmaxf(sg1, 1e-24f));                                    \
        gi2 = rsqrtf(fmaxf(sg2, 1e-24f));                                    \
    } while (0)

    int i = i0;
    for (; i + 2 <= i1; i += 2) {
        const int ba = batch[i];
        const int bb = batch[i + 1];          // sorted: ba <= bb

        // Batch all 8 h loads up front (MLP=8, evict-first streaming).
        const float4* pa1 = reinterpret_cast<const float4*>(h1 + (size_t)i * D);
        const float4* pa2 = reinterpret_cast<const float4*>(h2 + (size_t)i * D);
        const float4* pb1 = reinterpret_cast<const float4*>(h1 + (size_t)(i + 1) * D);
        const float4* pb2 = reinterpret_cast<const float4*>(h2 + (size_t)(i + 1) * D);
        float4 a0 = __ldcs(pa1 + lane), a1 = __ldcs(pa1 + lane + 32);
        float4 e0 = __ldcs(pa2 + lane), e1 = __ldcs(pa2 + lane + 32);
        float4 b0 = __ldcs(pb1 + lane), b1 = __ldcs(pb1 + lane + 32);
        float4 f0 = __ldcs(pb2 + lane), f1 = __ldcs(pb2 + lane + 32);

        if (ba != bcur) RELOAD_G(ba);         // warp-uniform, rare
        const float gia1 = gi1, gia2 = gi2;   // snapshot for row a

        float da1 = dot4(a0, cg0) + dot4(a1, cg1);
        float sa1 = dot4(a0, a0)  + dot4(a1, a1);
        float da2 = dot4(e0, fg0) + dot4(e1, fg1);
        float sa2 = dot4(e0, e0)  + dot4(e1, e1);

        if (bb != bcur) RELOAD_G(bb);         // row a's dots already formed

        float db1 = dot4(b0, cg0) + dot4(b1, cg1);
        float sb1 = dot4(b0, b0)  + dot4(b1, b1);
        float db2 = dot4(f0, fg0) + dot4(f1, fg1);
        float sb2 = dot4(f0, f0)  + dot4(f1, f1);

        // 8 interleaved reduction chains: high ILP hides SHFL latency.
#pragma unroll
        for (int off = 16; off > 0; off >>= 1) {
            da1 += __shfl_xor_sync(0xffffffffu, da1, off);
            sa1 += __shfl_xor_sync(0xffffffffu, sa1, off);
            da2 += __shfl_xor_sync(0xffffffffu, da2, off);
            sa2 += __shfl_xor_sync(0xffffffffu, sa2, off);
            db1 += __shfl_xor_sync(0xffffffffu, db1, off);
            sb1 += __shfl_xor_sync(0xffffffffu, sb1, off);
            db2 += __shfl_xor_sync(0xffffffffu, db2, off);
            sb2 += __shfl_xor_sync(0xffffffffu, sb2, off);
        }

        float va = da1 * rsqrtf(fmaxf(sa1, 1e-24f)) * gia2
                 + da2 * rsqrtf(fmaxf(sa2, 1e-24f)) * gia1;
        float vb = db1 * rsqrtf(fmaxf(sb1, 1e-24f)) * gi2
                 + db2 * rsqrtf(fmaxf(sb2, 1e-24f)) * gi1;
        acc += (double)va;
        acc += (double)vb;
    }

    if (i < i1) {                              // odd remainder row
        const int b = batch[i];
        const float4* ph1 = reinterpret_cast<const float4*>(h1 + (size_t)i * D);
        const float4* ph2 = reinterpret_cast<const float4*>(h2 + (size_t)i * D);
        float4 a0 = __ldcs(ph1 + lane), a1 = __ldcs(ph1 + lane + 32);
        float4 e0 = __ldcs(ph2 + lane), e1 = __ldcs(ph2 + lane + 32);

        if (b != bcur) RELOAD_G(b);

        float d1 = dot4(a0, cg0) + dot4(a1, cg1);
        float s1 = dot4(a0, a0)  + dot4(a1, a1);
        float d2 = dot4(e0, fg0) + dot4(e1, fg1);
        float s2 = dot4(e0, e0)  + dot4(e1, e1);
#pragma unroll
        for (int off = 16; off > 0; off >>= 1) {
            d1 += __shfl_xor_sync(0xffffffffu, d1, off);
            s1 += __shfl_xor_sync(0xffffffffu, s1, off);
            d2 += __shfl_xor_sync(0xffffffffu, d2, off);
            s2 += __shfl_xor_sync(0xffffffffu, s2, off);
        }
        float v = d1 * rsqrtf(fmaxf(s1, 1e-24f)) * gi2
                + d2 * rsqrtf(fmaxf(s2, 1e-24f)) * gi1;
        acc += (double)v;
    }
#undef RELOAD_G

    // ---- block-level partial ----
    __shared__ double sred[WPB];
    __shared__ bool   is_last;
    if (lane == 0) sred[wid] = acc;
    __syncthreads();
    if (threadIdx.x == 0) {
        double t = 0.0;
#pragma unroll
        for (int w = 0; w < WPB; ++w) t += sred[w];
        d_part[blockIdx.x] = t;
        __threadfence();
        unsigned prev = atomicAdd(&d_count, 1u);
        is_last = (prev == (unsigned)(NBLK - 1));
    }
    __syncthreads();

    // ---- last block: fixed-order deterministic final reduction ----
    if (is_last) {
        __shared__ double s[TPB];
        double t = 0.0;
        for (int k = threadIdx.x; k < NBLK; k += TPB)
            t += __ldcg(&d_part[k]);
        s[threadIdx.x] = t;
        __syncthreads();
#pragma unroll
        for (int off = TPB / 2; off > 0; off >>= 1) {
            if (threadIdx.x < off) s[threadIdx.x] += s[threadIdx.x + off];
            __syncthreads();
        }
        if (threadIdx.x == 0) {
            *out = (float)(s[0] / (double)G);
            d_count = 0;                       // reset for next graph replay
        }
    }
}

extern "C" void kernel_launch(void* const* d_in, const int* in_sizes, int n_in,
                              void* d_out, int out_size)
{
    const float* h1    = (const float*)d_in[0];
    const float* h2    = (const float*)d_in[1];
    const float* g1    = (const float*)d_in[2];
    const float* g2    = (const float*)d_in[3];
    const int*   batch = (const int*)d_in[4];   // jax default int32 (x64 disabled)

    const int N = in_sizes[4];          // rows in h1/h2
    const int G = in_sizes[2] / D;      // rows in g1/g2

    main_k<<<NBLK, TPB>>>(h1, h2, g1, g2, batch, (float*)d_out, N, G);
}